// round 15
// baseline (speedup 1.0000x reference)
#include <cuda_runtime.h>
#include <cuda_fp16.h>
#include <cstdint>

#define BB 4
#define HH 16
#define SSEQ 2048
#define DDIM 128
#define BM 128
#define BN 64
#define NTILES (SSEQ / BN)
#define NTH 256
#define N4PLANE (BB * HH * SSEQ * DDIM / 4)   // uint2 (4 fp16) count per plane
#define NMB (BB * SSEQ * NTILES)              // packed mask words (uint2 per row-tile)

// precomputed single-plane fp16 K and V (row-major, same indexing as inputs)
__device__ uint2 g_kh[N4PLANE], g_vh[N4PLANE];
// packed mask bits: g_mb[(b*SSEQ + row)*NTILES + kb] = 64 key-bits of that tile
__device__ uint2 g_mb[NMB];
// fp16 e scratch, [bh][row][key] row-major, stored as packed half2 words
__device__ uint32_t g_e[(size_t)BB * HH * SSEQ * SSEQ / 2];

// smem word layout (uint32 words, each = 2 fp16).
#define QST 136                                // Q/K/V row stride in fp16 elems
#define EST 72                                 // e-tile row stride in fp16 elems
#define Q_HI_W 0
#define KBUF_W(b) (8704 + (b) * 4352)          // 2 buffers (phase A)
#define VBUF_W(b) (17408 + (b) * 4352)         // 2 buffers (phase B)
#define EBUF_W(b) (26112 + (b) * 4608)         // 2 buffers (phase B), 128*36 words
#define SMEM_WORDS 35328
#define SMEM_BYTES (SMEM_WORDS * 4)            // 141,312 B

__device__ __forceinline__ uint32_t smem_u32(const void* p) {
    uint32_t a;
    asm("{ .reg .u64 t; cvta.to.shared.u64 t, %1; cvt.u32.u64 %0, t; }" : "=r"(a) : "l"(p));
    return a;
}

__device__ __forceinline__ void mma_f16(float c[4],
                                        uint32_t a0, uint32_t a1, uint32_t a2, uint32_t a3,
                                        uint32_t b0, uint32_t b1)
{
    asm volatile(
        "mma.sync.aligned.m16n8k16.row.col.f32.f16.f16.f32 "
        "{%0,%1,%2,%3}, {%4,%5,%6,%7}, {%8,%9}, {%0,%1,%2,%3};"
        : "+f"(c[0]), "+f"(c[1]), "+f"(c[2]), "+f"(c[3])
        : "r"(a0), "r"(a1), "r"(a2), "r"(a3), "r"(b0), "r"(b1));
}

__device__ __forceinline__ void ldsm4(uint32_t& r0, uint32_t& r1, uint32_t& r2, uint32_t& r3,
                                      uint32_t saddr)
{
    asm volatile("ldmatrix.sync.aligned.m8n8.x4.shared.b16 {%0,%1,%2,%3}, [%4];"
                 : "=r"(r0), "=r"(r1), "=r"(r2), "=r"(r3) : "r"(saddr));
}
__device__ __forceinline__ void ldsm4t(uint32_t& r0, uint32_t& r1, uint32_t& r2, uint32_t& r3,
                                       uint32_t saddr)
{
    asm volatile("ldmatrix.sync.aligned.m8n8.x4.trans.shared.b16 {%0,%1,%2,%3}, [%4];"
                 : "=r"(r0), "=r"(r1), "=r"(r2), "=r"(r3) : "r"(saddr));
}

#define CP16(dst, src) \
    asm volatile("cp.async.cg.shared.global [%0], [%1], 16;" :: "r"(dst), "l"(src))
#define CP_COMMIT() asm volatile("cp.async.commit_group;" ::: "memory")
#define CP_WAIT0()  asm volatile("cp.async.wait_group 0;" ::: "memory")

__device__ __forceinline__ uint32_t pack_h2(float x0, float x1)
{
    __half2 h = __floats2half2_rn(x0, x1);
    return *reinterpret_cast<uint32_t*>(&h);
}
__device__ __forceinline__ float ex2f(float x)
{
    float y;
    asm("ex2.approx.ftz.f32 %0, %1;" : "=f"(y) : "f"(x));
    return y;
}

// one-time K/V conversion: fp32 -> single fp16 plane each
__global__ __launch_bounds__(256)
void conv_kv(const float4* __restrict__ k, const float4* __restrict__ v)
{
    int i = blockIdx.x * blockDim.x + threadIdx.x;
    if (i >= N4PLANE) return;
    float4 x = k[i];
    g_kh[i] = make_uint2(pack_h2(x.x, x.y), pack_h2(x.z, x.w));
    float4 y = v[i];
    g_vh[i] = make_uint2(pack_h2(y.x, y.y), pack_h2(y.z, y.w));
}

// one-time mask packing: 64 int32 -> 64 bits (uint2) per (b,row,ktile)
__global__ __launch_bounds__(256)
void conv_mask(const int* __restrict__ mask)
{
    int t = blockIdx.x * blockDim.x + threadIdx.x;
    if (t >= NMB) return;
    int kb   = t & (NTILES - 1);
    int brow = t >> 5;                         // b*SSEQ + row
    const int4* src = (const int4*)(mask + (size_t)brow * SSEQ + kb * BN);
    uint32_t lo = 0, hi = 0;
    #pragma unroll
    for (int i = 0; i < 8; i++) {
        int4 m = src[i];
        uint32_t bits = (m.x ? 1u : 0u) | (m.y ? 2u : 0u) | (m.z ? 4u : 0u) | (m.w ? 8u : 0u);
        lo |= bits << (i * 4);
    }
    #pragma unroll
    for (int i = 8; i < 16; i++) {
        int4 m = src[i];
        uint32_t bits = (m.x ? 1u : 0u) | (m.y ? 2u : 0u) | (m.z ? 4u : 0u) | (m.w ? 8u : 0u);
        hi |= bits << (i * 4 - 32);
    }
    g_mb[t] = make_uint2(lo, hi);
}

// async-stage K tile: 4 cp.async/thread (phase A)
__device__ __forceinline__ void cp_tile_k(uint32_t sb, int dstbuf, size_t base_e, int tid)
{
    #pragma unroll
    for (int i = 0; i < 4; i++) {
        int chunk = i * NTH + tid;
        int row = chunk >> 4, c = chunk & 15;
        uint32_t smoff = (uint32_t)(row * 272 + c * 16);
        size_t gb = (base_e + (size_t)row * DDIM + c * 8) * 2;
        CP16(sb + KBUF_W(dstbuf) * 4 + smoff, (const char*)g_kh + gb);
    }
}
// async-stage V tile: 4 cp.async/thread (phase B)
__device__ __forceinline__ void cp_tile_v(uint32_t sb, int dstbuf, size_t base_e, int tid)
{
    #pragma unroll
    for (int i = 0; i < 4; i++) {
        int chunk = i * NTH + tid;
        int row = chunk >> 4, c = chunk & 15;
        uint32_t smoff = (uint32_t)(row * 272 + c * 16);
        size_t gb = (base_e + (size_t)row * DDIM + c * 8) * 2;
        CP16(sb + VBUF_W(dstbuf) * 4 + smoff, (const char*)g_vh + gb);
    }
}
// async-stage e tile [128 q-rows x 64 keys] fp16: 4 cp.async/thread (phase B)
__device__ __forceinline__ void cp_tile_e(uint32_t sb, int dstbuf, size_t row0_flat,
                                          int k0, int tid)
{
    #pragma unroll
    for (int i = 0; i < 4; i++) {
        int chunk = i * NTH + tid;                 // 0..1023
        int row = chunk >> 3, cc = chunk & 7;
        uint32_t smoff = (uint32_t)(row * 144 + cc * 16);
        size_t gb = ((row0_flat + row) * SSEQ + (size_t)k0) * 2 + cc * 16;
        CP16(sb + EBUF_W(dstbuf) * 4 + smoff, (const char*)g_e + gb);
    }
}

// score GEMM for one 64-key tile: sc[16 rows][64 keys], Q fragments in registers
__device__ __forceinline__ void score_mma(float (&sc)[8][4], uint32_t k_ad,
                                          const uint32_t (&qh)[8][4])
{
    #pragma unroll
    for (int j = 0; j < 8; j++)
        #pragma unroll
        for (int p = 0; p < 4; p++) sc[j][p] = 0.f;
    #pragma unroll
    for (int ks = 0; ks < 8; ks++) {
        uint32_t bf[4][4];
        #pragma unroll
        for (int jp = 0; jp < 4; jp++)
            ldsm4(bf[jp][0], bf[jp][1], bf[jp][2], bf[jp][3],
                  k_ad + ks * 32 + jp * (16 * QST * 2));
        #pragma unroll
        for (int jp = 0; jp < 4; jp++) {
            mma_f16(sc[2 * jp],     qh[ks][0], qh[ks][1], qh[ks][2], qh[ks][3],
                    bf[jp][0], bf[jp][1]);
            mma_f16(sc[2 * jp + 1], qh[ks][0], qh[ks][1], qh[ks][2], qh[ks][3],
                    bf[jp][2], bf[jp][3]);
        }
    }
}

// phase-A epilogue: masked exp -> rowsums + packed fp16 e stored to gmem
__device__ __forceinline__ void epiA(const float (&sc)[8][4], uint2 mb0, uint2 mb1,
                                     int tg, float& rs0, float& rs1,
                                     uint32_t* e0, uint32_t* e1, int k0)
{
    #pragma unroll
    for (int j = 0; j < 8; j++) {
        uint32_t w0 = (j < 4) ? mb0.x : mb0.y;
        uint32_t w1 = (j < 4) ? mb1.x : mb1.y;
        int sh = tg * 2 + (j & 3) * 8;
        float e00 = ((w0 >> sh) & 1)       ? ex2f(sc[j][0]) : 0.f;
        float e01 = ((w0 >> (sh + 1)) & 1) ? ex2f(sc[j][1]) : 0.f;
        float e10 = ((w1 >> sh) & 1)       ? ex2f(sc[j][2]) : 0.f;
        float e11 = ((w1 >> (sh + 1)) & 1) ? ex2f(sc[j][3]) : 0.f;
        rs0 += e00 + e01;
        rs1 += e10 + e11;
        int wi = k0 / 2 + tg + j * 4;
        e0[wi] = pack_h2(e00, e01);
        e1[wi] = pack_h2(e10, e11);
    }
}

// PV GEMM: o[16 rows][128 d] += e[16x64] * V[64x128], e-fragments from smem tile
__device__ __forceinline__ void pv_mma(float (&o)[16][4], uint32_t e_ad, uint32_t v_ad)
{
    uint32_t ef[4][4];
    #pragma unroll
    for (int ks = 0; ks < 4; ks++)
        ldsm4(ef[ks][0], ef[ks][1], ef[ks][2], ef[ks][3], e_ad + ks * 32);
    #pragma unroll
    for (int ks = 0; ks < 4; ks++) {
        #pragma unroll
        for (int gjn = 0; gjn < 2; gjn++) {
            uint32_t vf[4][4];
            #pragma unroll
            for (int j = 0; j < 4; j++) {
                int jnp = gjn * 4 + j;
                ldsm4t(vf[j][0], vf[j][1], vf[j][2], vf[j][3],
                       v_ad + ks * (16 * QST * 2) + jnp * 32);
            }
            #pragma unroll
            for (int j = 0; j < 4; j++) {
                int jnp = gjn * 4 + j;
                mma_f16(o[2 * jnp],     ef[ks][0], ef[ks][1], ef[ks][2], ef[ks][3],
                        vf[j][0], vf[j][1]);
                mma_f16(o[2 * jnp + 1], ef[ks][0], ef[ks][1], ef[ks][2], ef[ks][3],
                        vf[j][2], vf[j][3]);
            }
        }
    }
}

__global__ __launch_bounds__(NTH, 1)
void attn_mma(const float* __restrict__ q,
              float* __restrict__ out,
              float* __restrict__ attn)
{
    extern __shared__ uint32_t SW[];
    const uint32_t sb = smem_u32(SW);

    const int tid  = threadIdx.x;
    const int lane = tid & 31;
    const int w16  = (tid >> 5) * 16;
    const int g    = lane >> 2;
    const int tg   = lane & 3;

    const int h      = blockIdx.x;
    const int qblock = blockIdx.y;
    const int b      = blockIdx.z;
    const int bh     = b * HH + h;
    const int q0     = qblock * BM;
    const size_t head = (size_t)bh * SSEQ * DDIM;

    // ---- async-stage K tile 0 ----
    cp_tile_k(sb, 0, head, tid);
    CP_COMMIT();

    // ---- stage Q tile (128x128), pre-scaled by scale*log2e, single fp16 plane ----
    {
        const float qsc = 0.08838834764831843f * 1.4426950408889634f;
        const float4* qp4 = (const float4*)(q + head + (size_t)q0 * DDIM);
        #pragma unroll
        for (int it = 0; it < 16; it++) {
            int idx = it * NTH + tid;
            int row = idx >> 5;
            int c4  = (idx & 31) << 2;
            float4 x = qp4[idx];
            int w = (row * QST + c4) >> 1;
            *(uint2*)(SW + Q_HI_W + w) =
                make_uint2(pack_h2(x.x * qsc, x.y * qsc), pack_h2(x.z * qsc, x.w * qsc));
        }
    }

    // ldmatrix lane-address bases (byte offsets within a tile)
    const uint32_t a_byte  = (uint32_t)(((w16 + (lane & 15)) * QST + ((lane & 16) ? 8 : 0)) * 2);
    const uint32_t qhi_ad  = sb + Q_HI_W * 4 + a_byte;
    const uint32_t bk_byte = (uint32_t)((((lane & 7) + ((lane & 16) ? 8 : 0)) * QST +
                                         ((lane & 8) ? 8 : 0)) * 2);
    const uint32_t bv_byte = (uint32_t)((((lane & 7) + ((lane & 8) ? 8 : 0)) * QST) * 2 +
                                        ((lane & 16) ? 16 : 0));
    const uint32_t ea_byte = (uint32_t)(((w16 + (lane & 15)) * EST + ((lane & 16) ? 8 : 0)) * 2);

    const int r0 = q0 + w16 + g;
    const size_t row0_flat = (size_t)bh * SSEQ + q0;          // e-tile base q-row
    const uint2* mbp = g_mb + ((size_t)b * SSEQ + r0) * NTILES;
    float* a0p = attn + ((size_t)bh * SSEQ + r0) * SSEQ;
    float* a1p = a0p + (size_t)8 * SSEQ;
    uint32_t* e0p = g_e + ((size_t)bh * SSEQ + r0) * (SSEQ / 2);
    uint32_t* e1p = e0p + (size_t)8 * (SSEQ / 2);

    float rsum0 = 0.f, rsum1 = 0.f;
    float scA[8][4], scB[8][4];

    CP_WAIT0();
    __syncthreads();

    // ---- hoist loop-invariant Q A-fragments ----
    uint32_t qh[8][4];
    #pragma unroll
    for (int ks = 0; ks < 8; ks++)
        ldsm4(qh[ks][0], qh[ks][1], qh[ks][2], qh[ks][3], qhi_ad + ks * 32);

    // ====== PHASE A: rowsums + e materialization, epilogue pipelined 1 tile behind ======
    cp_tile_k(sb, 1, head + (size_t)BN * DDIM, tid);
    CP_COMMIT();
    uint2 pm0 = mbp[0], pm1 = mbp[8 * NTILES];
    score_mma(scA, sb + KBUF_W(0) * 4 + bk_byte, qh);

    for (int kb = 1; kb + 1 < NTILES; kb += 2) {
        CP_WAIT0();
        __syncthreads();
        cp_tile_k(sb, (kb + 1) & 1, head + (size_t)(kb + 1) * BN * DDIM, tid);
        CP_COMMIT();
        uint2 nm0 = mbp[kb], nm1 = mbp[8 * NTILES + kb];
        score_mma(scB, sb + KBUF_W(kb & 1) * 4 + bk_byte, qh);
        epiA(scA, pm0, pm1, tg, rsum0, rsum1, e0p, e1p, (kb - 1) * BN);
        pm0 = nm0; pm1 = nm1;

        CP_WAIT0();
        __syncthreads();
        if (kb + 2 < NTILES) {
            cp_tile_k(sb, (kb + 2) & 1, head + (size_t)(kb + 2) * BN * DDIM, tid);
            CP_COMMIT();
        }
        nm0 = mbp[kb + 1]; nm1 = mbp[8 * NTILES + kb + 1];
        score_mma(scA, sb + KBUF_W((kb + 1) & 1) * 4 + bk_byte, qh);
        epiA(scB, pm0, pm1, tg, rsum0, rsum1, e0p, e1p, kb * BN);
        pm0 = nm0; pm1 = nm1;
    }
    CP_WAIT0();
    __syncthreads();
    {
        uint2 nm0 = mbp[NTILES - 1], nm1 = mbp[8 * NTILES + NTILES - 1];
        score_mma(scB, sb + KBUF_W((NTILES - 1) & 1) * 4 + bk_byte, qh);
        epiA(scA, pm0, pm1, tg, rsum0, rsum1, e0p, e1p, (NTILES - 2) * BN);
        epiA(scB, nm0, nm1, tg, rsum0, rsum1, e0p, e1p, (NTILES - 1) * BN);
    }

    // rowsum butterfly -> inv in registers
    rsum0 += __shfl_xor_sync(0xFFFFFFFF, rsum0, 1);
    rsum0 += __shfl_xor_sync(0xFFFFFFFF, rsum0, 2);
    rsum1 += __shfl_xor_sync(0xFFFFFFFF, rsum1, 1);
    rsum1 += __shfl_xor_sync(0xFFFFFFFF, rsum1, 2);
    const float inv0 = 1.0f / rsum0;
    const float inv1 = 1.0f / rsum1;

    // ====== PHASE B: PV from materialized e + normalized attn write; no K, no exp ======
    float o[16][4];
    #pragma unroll
    for (int jn = 0; jn < 16; jn++)
        #pragma unroll
        for (int p = 0; p < 4; p++) o[jn][p] = 0.f;

    __syncthreads();                 // all phase-A e stores issued; CTA-local visibility
    cp_tile_e(sb, 0, row0_flat, 0, tid);
    cp_tile_v(sb, 0, head, tid);
    CP_COMMIT();
    CP_WAIT0();
    __syncthreads();

    for (int kb = 0; kb < NTILES; kb++) {
        const int buf = kb & 1;
        const int k0  = kb * BN;
        const bool pf = (kb + 1 < NTILES);

        if (pf) {
            cp_tile_e(sb, buf ^ 1, row0_flat, k0 + BN, tid);
            cp_tile_v(sb, buf ^ 1, head + (size_t)(k0 + BN) * DDIM, tid);
            CP_COMMIT();
        }

        // ---- PV MMAs from e/V smem tiles ----
        pv_mma(o, sb + EBUF_W(buf) * 4 + ea_byte, sb + VBUF_W(buf) * 4 + bv_byte);

        // ---- attn write: read e from smem, scale by inv (no exp, no mask) ----
        {
            const uint32_t* eb = SW + EBUF_W(buf);
            const int wr0 = (w16 + g) * (EST / 2);          // row word base
            const int wr1 = (w16 + g + 8) * (EST / 2);
            #pragma unroll
            for (int j = 0; j < 8; j++) {
                int wc = tg + j * 4;
                float2 f0 = __half22float2(*(const __half2*)(eb + wr0 + wc));
                float2 f1 = __half22float2(*(const __half2*)(eb + wr1 + wc));
                const int c = k0 + tg * 2 + j * 8;
                *(float2*)(a0p + c) = make_float2(f0.x * inv0, f0.y * inv0);
                *(float2*)(a1p + c) = make_float2(f1.x * inv1, f1.y * inv1);
            }
        }

        if (pf) CP_WAIT0();
        __syncthreads();
    }

    // ---- normalized out ----
    float* o0p = out + ((size_t)bh * SSEQ + r0) * DDIM;
    float* o1p = o0p + (size_t)8 * DDIM;
    #pragma unroll
    for (int jn = 0; jn < 16; jn++) {
        const int c = jn * 8 + tg * 2;
        *(float2*)(o0p + c) = make_float2(o[jn][0] * inv0, o[jn][1] * inv0);
        *(float2*)(o1p + c) = make_float2(o[jn][2] * inv1, o[jn][3] * inv1);
    }
}

extern "C" void kernel_launch(void* const* d_in, const int* in_sizes, int n_in,
                              void* d_out, int out_size)
{
    const float* q    = (const float*)d_in[0];
    const float* k    = (const float*)d_in[1];
    const float* v    = (const float*)d_in[2];
    const int*   mask = (const int*)d_in[3];

    float* out  = (float*)d_out;
    float* attn = out + (size_t)BB * HH * SSEQ * DDIM;

    // one-time (per launch) precompute: K/V fp16 planes + packed mask bits
    conv_kv<<<N4PLANE / 256, 256>>>((const float4*)k, (const float4*)v);
    conv_mask<<<NMB / 256, 256>>>(mask);

    cudaFuncSetAttribute(attn_mma, cudaFuncAttributeMaxDynamicSharedMemorySize, SMEM_BYTES);
    dim3 grid(HH, SSEQ / BM, BB);       // h fastest: concurrent CTAs share K/V + mask in L2
    attn_mma<<<grid, NTH, SMEM_BYTES>>>(q, out, attn);
}

// round 16
// speedup vs baseline: 1.0679x; 1.0679x over previous
#include <cuda_runtime.h>
#include <cuda_fp16.h>
#include <cstdint>

#define BB 4
#define HH 16
#define SSEQ 2048
#define DDIM 128
#define BM 128
#define BN 64
#define NTILES (SSEQ / BN)
#define NTH 256
#define N4PLANE (BB * HH * SSEQ * DDIM / 4)   // uint2 (4 fp16) count per plane
#define NMB (BB * SSEQ * NTILES)              // packed mask words (uint2 per row-tile)

__device__ float g_inv_rowsum[BB * HH * SSEQ];
// precomputed single-plane fp16 K and V (row-major, same indexing as inputs)
__device__ uint2 g_kh[N4PLANE], g_vh[N4PLANE];
// packed mask bits: g_mb[(b*SSEQ + row)*NTILES + kb] = 64 key-bits of that tile
__device__ uint2 g_mb[NMB];
// fp16 e scratch, [bh][row][key] row-major, stored as packed half2 words
__device__ uint32_t g_e[(size_t)BB * HH * SSEQ * SSEQ / 2];

// strides (fp16 elems)
#define QST 136
#define EST 72

// kernel A smem (words): Q plane + 2 K buffers
#define QA_W 0
#define KA_W(b) (8704 + (b) * 4352)
#define SMEM_A_BYTES (17408 * 4)               // 69,632 B

// kernel B smem (words): 2 e buffers + 2 V buffers
#define EB_W(b) ((b) * 4608)
#define VB_W(b) (9216 + (b) * 4352)
#define SMEM_B_BYTES (17920 * 4)               // 71,680 B

__device__ __forceinline__ uint32_t smem_u32(const void* p) {
    uint32_t a;
    asm("{ .reg .u64 t; cvta.to.shared.u64 t, %1; cvt.u32.u64 %0, t; }" : "=r"(a) : "l"(p));
    return a;
}

__device__ __forceinline__ void mma_f16(float c[4],
                                        uint32_t a0, uint32_t a1, uint32_t a2, uint32_t a3,
                                        uint32_t b0, uint32_t b1)
{
    asm volatile(
        "mma.sync.aligned.m16n8k16.row.col.f32.f16.f16.f32 "
        "{%0,%1,%2,%3}, {%4,%5,%6,%7}, {%8,%9}, {%0,%1,%2,%3};"
        : "+f"(c[0]), "+f"(c[1]), "+f"(c[2]), "+f"(c[3])
        : "r"(a0), "r"(a1), "r"(a2), "r"(a3), "r"(b0), "r"(b1));
}

__device__ __forceinline__ void ldsm4(uint32_t& r0, uint32_t& r1, uint32_t& r2, uint32_t& r3,
                                      uint32_t saddr)
{
    asm volatile("ldmatrix.sync.aligned.m8n8.x4.shared.b16 {%0,%1,%2,%3}, [%4];"
                 : "=r"(r0), "=r"(r1), "=r"(r2), "=r"(r3) : "r"(saddr));
}
__device__ __forceinline__ void ldsm4t(uint32_t& r0, uint32_t& r1, uint32_t& r2, uint32_t& r3,
                                       uint32_t saddr)
{
    asm volatile("ldmatrix.sync.aligned.m8n8.x4.trans.shared.b16 {%0,%1,%2,%3}, [%4];"
                 : "=r"(r0), "=r"(r1), "=r"(r2), "=r"(r3) : "r"(saddr));
}

#define CP16(dst, src) \
    asm volatile("cp.async.cg.shared.global [%0], [%1], 16;" :: "r"(dst), "l"(src))
#define CP_COMMIT() asm volatile("cp.async.commit_group;" ::: "memory")
#define CP_WAIT0()  asm volatile("cp.async.wait_group 0;" ::: "memory")

__device__ __forceinline__ uint32_t pack_h2(float x0, float x1)
{
    __half2 h = __floats2half2_rn(x0, x1);
    return *reinterpret_cast<uint32_t*>(&h);
}
__device__ __forceinline__ float ex2f(float x)
{
    float y;
    asm("ex2.approx.ftz.f32 %0, %1;" : "=f"(y) : "f"(x));
    return y;
}

// one-time K/V conversion: fp32 -> single fp16 plane each
__global__ __launch_bounds__(256)
void conv_kv(const float4* __restrict__ k, const float4* __restrict__ v)
{
    int i = blockIdx.x * blockDim.x + threadIdx.x;
    if (i >= N4PLANE) return;
    float4 x = k[i];
    g_kh[i] = make_uint2(pack_h2(x.x, x.y), pack_h2(x.z, x.w));
    float4 y = v[i];
    g_vh[i] = make_uint2(pack_h2(y.x, y.y), pack_h2(y.z, y.w));
}

// one-time mask packing: 64 int32 -> 64 bits (uint2) per (b,row,ktile)
__global__ __launch_bounds__(256)
void conv_mask(const int* __restrict__ mask)
{
    int t = blockIdx.x * blockDim.x + threadIdx.x;
    if (t >= NMB) return;
    int kb   = t & (NTILES - 1);
    int brow = t >> 5;
    const int4* src = (const int4*)(mask + (size_t)brow * SSEQ + kb * BN);
    uint32_t lo = 0, hi = 0;
    #pragma unroll
    for (int i = 0; i < 8; i++) {
        int4 m = src[i];
        uint32_t bits = (m.x ? 1u : 0u) | (m.y ? 2u : 0u) | (m.z ? 4u : 0u) | (m.w ? 8u : 0u);
        lo |= bits << (i * 4);
    }
    #pragma unroll
    for (int i = 8; i < 16; i++) {
        int4 m = src[i];
        uint32_t bits = (m.x ? 1u : 0u) | (m.y ? 2u : 0u) | (m.z ? 4u : 0u) | (m.w ? 8u : 0u);
        hi |= bits << (i * 4 - 32);
    }
    g_mb[t] = make_uint2(lo, hi);
}

// ============================ KERNEL A: scores -> e + rowsums ============================
__global__ __launch_bounds__(NTH, 2)
void attn_a(const float* __restrict__ q)
{
    extern __shared__ uint32_t SW[];
    const uint32_t sb = smem_u32(SW);

    const int tid  = threadIdx.x;
    const int lane = tid & 31;
    const int w16  = (tid >> 5) * 16;
    const int g    = lane >> 2;
    const int tg   = lane & 3;

    const int h      = blockIdx.x;
    const int qblock = blockIdx.y;
    const int b      = blockIdx.z;
    const int bh     = b * HH + h;
    const int q0     = qblock * BM;
    const size_t head = (size_t)bh * SSEQ * DDIM;

    // stage K tile 0
    #pragma unroll
    for (int i = 0; i < 4; i++) {
        int chunk = i * NTH + tid;
        int row = chunk >> 4, c = chunk & 15;
        CP16(sb + KA_W(0) * 4 + row * 272 + c * 16,
             (const char*)g_kh + (head + (size_t)row * DDIM + c * 8) * 2);
    }
    CP_COMMIT();

    // stage Q tile, pre-scaled by scale*log2e, single fp16 plane
    {
        const float qsc = 0.08838834764831843f * 1.4426950408889634f;
        const float4* qp4 = (const float4*)(q + head + (size_t)q0 * DDIM);
        #pragma unroll
        for (int it = 0; it < 16; it++) {
            int idx = it * NTH + tid;
            int row = idx >> 5;
            int c4  = (idx & 31) << 2;
            float4 x = qp4[idx];
            int w = (row * QST + c4) >> 1;
            *(uint2*)(SW + QA_W + w) =
                make_uint2(pack_h2(x.x * qsc, x.y * qsc), pack_h2(x.z * qsc, x.w * qsc));
        }
    }

    const uint32_t a_byte  = (uint32_t)(((w16 + (lane & 15)) * QST + ((lane & 16) ? 8 : 0)) * 2);
    const uint32_t qhi_ad  = sb + QA_W * 4 + a_byte;
    const uint32_t bk_byte = (uint32_t)((((lane & 7) + ((lane & 16) ? 8 : 0)) * QST +
                                         ((lane & 8) ? 8 : 0)) * 2);

    const int r0 = q0 + w16 + g;
    const uint2* mbp = g_mb + ((size_t)b * SSEQ + r0) * NTILES;
    uint32_t* e0p = g_e + ((size_t)bh * SSEQ + r0) * (SSEQ / 2);
    uint32_t* e1p = e0p + (size_t)8 * (SSEQ / 2);

    float rsum0 = 0.f, rsum1 = 0.f;

    CP_WAIT0();
    __syncthreads();

    uint32_t qh[8][4];
    #pragma unroll
    for (int ks = 0; ks < 8; ks++)
        ldsm4(qh[ks][0], qh[ks][1], qh[ks][2], qh[ks][3], qhi_ad + ks * 32);

    for (int kb = 0; kb < NTILES; kb++) {
        const int buf = kb & 1;
        const int k0  = kb * BN;
        const bool pf = (kb + 1 < NTILES);

        if (pf) {
            #pragma unroll
            for (int i = 0; i < 4; i++) {
                int chunk = i * NTH + tid;
                int row = chunk >> 4, c = chunk & 15;
                CP16(sb + KA_W(buf ^ 1) * 4 + row * 272 + c * 16,
                     (const char*)g_kh +
                     (head + (size_t)(k0 + BN) * DDIM + (size_t)row * DDIM + c * 8) * 2);
            }
            CP_COMMIT();
        }

        const uint2 mb0 = mbp[kb];
        const uint2 mb1 = mbp[8 * NTILES + kb];
        const uint32_t k_ad = sb + KA_W(buf) * 4 + bk_byte;

        // score GEMM
        float sc[8][4];
        #pragma unroll
        for (int j = 0; j < 8; j++)
            #pragma unroll
            for (int p = 0; p < 4; p++) sc[j][p] = 0.f;
        #pragma unroll
        for (int ks = 0; ks < 8; ks++) {
            uint32_t bf[4][4];
            #pragma unroll
            for (int jp = 0; jp < 4; jp++)
                ldsm4(bf[jp][0], bf[jp][1], bf[jp][2], bf[jp][3],
                      k_ad + ks * 32 + jp * (16 * QST * 2));
            #pragma unroll
            for (int jp = 0; jp < 4; jp++) {
                mma_f16(sc[2 * jp],     qh[ks][0], qh[ks][1], qh[ks][2], qh[ks][3],
                        bf[jp][0], bf[jp][1]);
                mma_f16(sc[2 * jp + 1], qh[ks][0], qh[ks][1], qh[ks][2], qh[ks][3],
                        bf[jp][2], bf[jp][3]);
            }
        }

        // epilogue: masked exp -> rowsums + fp16 e to gmem
        #pragma unroll
        for (int j = 0; j < 8; j++) {
            uint32_t w0 = (j < 4) ? mb0.x : mb0.y;
            uint32_t w1 = (j < 4) ? mb1.x : mb1.y;
            int sh = tg * 2 + (j & 3) * 8;
            float e00 = ((w0 >> sh) & 1)       ? ex2f(sc[j][0]) : 0.f;
            float e01 = ((w0 >> (sh + 1)) & 1) ? ex2f(sc[j][1]) : 0.f;
            float e10 = ((w1 >> sh) & 1)       ? ex2f(sc[j][2]) : 0.f;
            float e11 = ((w1 >> (sh + 1)) & 1) ? ex2f(sc[j][3]) : 0.f;
            rsum0 += e00 + e01;
            rsum1 += e10 + e11;
            int wi = k0 / 2 + tg + j * 4;
            e0p[wi] = pack_h2(e00, e01);
            e1p[wi] = pack_h2(e10, e11);
        }

        if (pf) CP_WAIT0();
        __syncthreads();
    }

    rsum0 += __shfl_xor_sync(0xFFFFFFFF, rsum0, 1);
    rsum0 += __shfl_xor_sync(0xFFFFFFFF, rsum0, 2);
    rsum1 += __shfl_xor_sync(0xFFFFFFFF, rsum1, 1);
    rsum1 += __shfl_xor_sync(0xFFFFFFFF, rsum1, 2);
    if (tg == 0) {
        g_inv_rowsum[(size_t)bh * SSEQ + r0]     = 1.0f / rsum0;
        g_inv_rowsum[(size_t)bh * SSEQ + r0 + 8] = 1.0f / rsum1;
    }
}

// ============================ KERNEL B: PV + normalized attn ============================
__global__ __launch_bounds__(NTH, 2)
void attn_b(float* __restrict__ out, float* __restrict__ attn)
{
    extern __shared__ uint32_t SW[];
    const uint32_t sb = smem_u32(SW);

    const int tid  = threadIdx.x;
    const int lane = tid & 31;
    const int w16  = (tid >> 5) * 16;
    const int g    = lane >> 2;
    const int tg   = lane & 3;

    const int h      = blockIdx.x;
    const int qblock = blockIdx.y;
    const int b      = blockIdx.z;
    const int bh     = b * HH + h;
    const int q0     = qblock * BM;
    const size_t head = (size_t)bh * SSEQ * DDIM;
    const size_t row0_flat = (size_t)bh * SSEQ + q0;

    const uint32_t bv_byte = (uint32_t)((((lane & 7) + ((lane & 8) ? 8 : 0)) * QST) * 2 +
                                        ((lane & 16) ? 16 : 0));
    const uint32_t ea_byte = (uint32_t)(((w16 + (lane & 15)) * EST + ((lane & 16) ? 8 : 0)) * 2);

    const int r0 = q0 + w16 + g;
    float* a0p = attn + ((size_t)bh * SSEQ + r0) * SSEQ;
    float* a1p = a0p + (size_t)8 * SSEQ;
    const float inv0 = g_inv_rowsum[(size_t)bh * SSEQ + r0];
    const float inv1 = g_inv_rowsum[(size_t)bh * SSEQ + r0 + 8];

    float o[16][4];
    #pragma unroll
    for (int jn = 0; jn < 16; jn++)
        #pragma unroll
        for (int p = 0; p < 4; p++) o[jn][p] = 0.f;

    // stage e/V tile 0
    #pragma unroll
    for (int i = 0; i < 4; i++) {
        int chunk = i * NTH + tid;
        {   // e: 128 rows x 8 16B-chunks
            int row = chunk >> 3, cc = chunk & 7;
            CP16(sb + EB_W(0) * 4 + row * 144 + cc * 16,
                 (const char*)g_e + ((row0_flat + row) * SSEQ) * 2 + cc * 16);
        }
        {   // V: 64 rows x 16 16B-chunks
            int row = chunk >> 4, c = chunk & 15;
            CP16(sb + VB_W(0) * 4 + row * 272 + c * 16,
                 (const char*)g_vh + (head + (size_t)row * DDIM + c * 8) * 2);
        }
    }
    CP_COMMIT();
    CP_WAIT0();
    __syncthreads();

    for (int kb = 0; kb < NTILES; kb++) {
        const int buf = kb & 1;
        const int k0  = kb * BN;
        const bool pf = (kb + 1 < NTILES);

        if (pf) {
            #pragma unroll
            for (int i = 0; i < 4; i++) {
                int chunk = i * NTH + tid;
                {
                    int row = chunk >> 3, cc = chunk & 7;
                    CP16(sb + EB_W(buf ^ 1) * 4 + row * 144 + cc * 16,
                         (const char*)g_e + ((row0_flat + row) * SSEQ + (size_t)(k0 + BN)) * 2
                         + cc * 16);
                }
                {
                    int row = chunk >> 4, c = chunk & 15;
                    CP16(sb + VB_W(buf ^ 1) * 4 + row * 272 + c * 16,
                         (const char*)g_vh +
                         (head + (size_t)(k0 + BN) * DDIM + (size_t)row * DDIM + c * 8) * 2);
                }
            }
            CP_COMMIT();
        }

        // PV MMAs from e/V smem tiles
        {
            const uint32_t e_ad = sb + EB_W(buf) * 4 + ea_byte;
            const uint32_t v_ad = sb + VB_W(buf) * 4 + bv_byte;
            uint32_t ef[4][4];
            #pragma unroll
            for (int ks = 0; ks < 4; ks++)
                ldsm4(ef[ks][0], ef[ks][1], ef[ks][2], ef[ks][3], e_ad + ks * 32);
            #pragma unroll
            for (int ks = 0; ks < 4; ks++) {
                #pragma unroll
                for (int gjn = 0; gjn < 2; gjn++) {
                    uint32_t vf[4][4];
                    #pragma unroll
                    for (int j = 0; j < 4; j++) {
                        int jnp = gjn * 4 + j;
                        ldsm4t(vf[j][0], vf[j][1], vf[j][2], vf[j][3],
                               v_ad + ks * (16 * QST * 2) + jnp * 32);
                    }
                    #pragma unroll
                    for (int j = 0; j < 4; j++) {
                        int jnp = gjn * 4 + j;
                        mma_f16(o[2 * jnp],     ef[ks][0], ef[ks][1], ef[ks][2], ef[ks][3],
                                vf[j][0], vf[j][1]);
                        mma_f16(o[2 * jnp + 1], ef[ks][0], ef[ks][1], ef[ks][2], ef[ks][3],
                                vf[j][2], vf[j][3]);
                    }
                }
            }
        }

        // attn write: read e from smem, scale by inv
        {
            const uint32_t* eb = SW + EB_W(buf);
            const int wr0 = (w16 + g) * (EST / 2);
            const int wr1 = (w16 + g + 8) * (EST / 2);
            #pragma unroll
            for (int j = 0; j < 8; j++) {
                int wc = tg + j * 4;
                float2 f0 = __half22float2(*(const __half2*)(eb + wr0 + wc));
                float2 f1 = __half22float2(*(const __half2*)(eb + wr1 + wc));
                const int c = k0 + tg * 2 + j * 8;
                *(float2*)(a0p + c) = make_float2(f0.x * inv0, f0.y * inv0);
                *(float2*)(a1p + c) = make_float2(f1.x * inv1, f1.y * inv1);
            }
        }

        if (pf) CP_WAIT0();
        __syncthreads();
    }

    // normalized out
    float* o0p = out + ((size_t)bh * SSEQ + r0) * DDIM;
    float* o1p = o0p + (size_t)8 * DDIM;
    #pragma unroll
    for (int jn = 0; jn < 16; jn++) {
        const int c = jn * 8 + tg * 2;
        *(float2*)(o0p + c) = make_float2(o[jn][0] * inv0, o[jn][1] * inv0);
        *(float2*)(o1p + c) = make_float2(o[jn][2] * inv1, o[jn][3] * inv1);
    }
}

extern "C" void kernel_launch(void* const* d_in, const int* in_sizes, int n_in,
                              void* d_out, int out_size)
{
    const float* q    = (const float*)d_in[0];
    const float* k    = (const float*)d_in[1];
    const float* v    = (const float*)d_in[2];
    const int*   mask = (const int*)d_in[3];

    float* out  = (float*)d_out;
    float* attn = out + (size_t)BB * HH * SSEQ * DDIM;

    conv_kv<<<N4PLANE / 256, 256>>>((const float4*)k, (const float4*)v);
    conv_mask<<<NMB / 256, 256>>>(mask);

    cudaFuncSetAttribute(attn_a, cudaFuncAttributeMaxDynamicSharedMemorySize, SMEM_A_BYTES);
    cudaFuncSetAttribute(attn_b, cudaFuncAttributeMaxDynamicSharedMemorySize, SMEM_B_BYTES);

    dim3 grid(HH, SSEQ / BM, BB);
    attn_a<<<grid, NTH, SMEM_A_BYTES>>>(q);
    attn_b<<<grid, NTH, SMEM_B_BYTES>>>(out, attn);
}

// round 17
// speedup vs baseline: 1.0731x; 1.0049x over previous
#include <cuda_runtime.h>
#include <cuda_fp16.h>
#include <cstdint>

#define BB 4
#define HH 16
#define SSEQ 2048
#define DDIM 128
#define BM 128
#define BN 64
#define NTILES (SSEQ / BN)
#define NTH 256
#define N4PLANE (BB * HH * SSEQ * DDIM / 4)   // uint2 (4 fp16) count per plane
#define NMB (BB * SSEQ * NTILES)              // packed mask words (uint2 per row-tile)

__device__ float g_inv_rowsum[BB * HH * SSEQ];
// precomputed single-plane fp16 K and V (row-major, same indexing as inputs)
__device__ uint2 g_kh[N4PLANE], g_vh[N4PLANE];
// packed mask bits: g_mb[(b*SSEQ + row)*NTILES + kb] = 64 key-bits of that tile
__device__ uint2 g_mb[NMB];
// fp16 e scratch, [bh][row][key] row-major, stored as packed half2 words
__device__ uint32_t g_e[(size_t)BB * HH * SSEQ * SSEQ / 2];

// strides (fp16 elems)
#define QST 136
#define EST 72

// kernel A smem (words): Q plane + 2 K buffers
#define QA_W 0
#define KA_W(b) (8704 + (b) * 4352)
#define SMEM_A_BYTES (17408 * 4)               // 69,632 B

// kernel B smem (words): 2 e buffers + 2 V buffers
#define EB_W(b) ((b) * 4608)
#define VB_W(b) (9216 + (b) * 4352)
#define SMEM_B_BYTES (17920 * 4)               // 71,680 B

__device__ __forceinline__ uint32_t smem_u32(const void* p) {
    uint32_t a;
    asm("{ .reg .u64 t; cvta.to.shared.u64 t, %1; cvt.u32.u64 %0, t; }" : "=r"(a) : "l"(p));
    return a;
}

__device__ __forceinline__ void mma_f16(float c[4],
                                        uint32_t a0, uint32_t a1, uint32_t a2, uint32_t a3,
                                        uint32_t b0, uint32_t b1)
{
    asm volatile(
        "mma.sync.aligned.m16n8k16.row.col.f32.f16.f16.f32 "
        "{%0,%1,%2,%3}, {%4,%5,%6,%7}, {%8,%9}, {%0,%1,%2,%3};"
        : "+f"(c[0]), "+f"(c[1]), "+f"(c[2]), "+f"(c[3])
        : "r"(a0), "r"(a1), "r"(a2), "r"(a3), "r"(b0), "r"(b1));
}

__device__ __forceinline__ void ldsm4(uint32_t& r0, uint32_t& r1, uint32_t& r2, uint32_t& r3,
                                      uint32_t saddr)
{
    asm volatile("ldmatrix.sync.aligned.m8n8.x4.shared.b16 {%0,%1,%2,%3}, [%4];"
                 : "=r"(r0), "=r"(r1), "=r"(r2), "=r"(r3) : "r"(saddr));
}
__device__ __forceinline__ void ldsm4t(uint32_t& r0, uint32_t& r1, uint32_t& r2, uint32_t& r3,
                                       uint32_t saddr)
{
    asm volatile("ldmatrix.sync.aligned.m8n8.x4.trans.shared.b16 {%0,%1,%2,%3}, [%4];"
                 : "=r"(r0), "=r"(r1), "=r"(r2), "=r"(r3) : "r"(saddr));
}

#define CP16(dst, src) \
    asm volatile("cp.async.cg.shared.global [%0], [%1], 16;" :: "r"(dst), "l"(src))
#define CP_COMMIT() asm volatile("cp.async.commit_group;" ::: "memory")
#define CP_WAIT0()  asm volatile("cp.async.wait_group 0;" ::: "memory")

__device__ __forceinline__ uint32_t pack_h2(float x0, float x1)
{
    __half2 h = __floats2half2_rn(x0, x1);
    return *reinterpret_cast<uint32_t*>(&h);
}
__device__ __forceinline__ float ex2f(float x)
{
    float y;
    asm("ex2.approx.ftz.f32 %0, %1;" : "=f"(y) : "f"(x));
    return y;
}

// one-time K/V conversion: fp32 -> single fp16 plane each
__global__ __launch_bounds__(256)
void conv_kv(const float4* __restrict__ k, const float4* __restrict__ v)
{
    int i = blockIdx.x * blockDim.x + threadIdx.x;
    if (i >= N4PLANE) return;
    float4 x = k[i];
    g_kh[i] = make_uint2(pack_h2(x.x, x.y), pack_h2(x.z, x.w));
    float4 y = v[i];
    g_vh[i] = make_uint2(pack_h2(y.x, y.y), pack_h2(y.z, y.w));
}

// one-time mask packing: 64 int32 -> 64 bits (uint2) per (b,row,ktile)
__global__ __launch_bounds__(256)
void conv_mask(const int* __restrict__ mask)
{
    int t = blockIdx.x * blockDim.x + threadIdx.x;
    if (t >= NMB) return;
    int kb   = t & (NTILES - 1);
    int brow = t >> 5;
    const int4* src = (const int4*)(mask + (size_t)brow * SSEQ + kb * BN);
    uint32_t lo = 0, hi = 0;
    #pragma unroll
    for (int i = 0; i < 8; i++) {
        int4 m = src[i];
        uint32_t bits = (m.x ? 1u : 0u) | (m.y ? 2u : 0u) | (m.z ? 4u : 0u) | (m.w ? 8u : 0u);
        lo |= bits << (i * 4);
    }
    #pragma unroll
    for (int i = 8; i < 16; i++) {
        int4 m = src[i];
        uint32_t bits = (m.x ? 1u : 0u) | (m.y ? 2u : 0u) | (m.z ? 4u : 0u) | (m.w ? 8u : 0u);
        hi |= bits << (i * 4 - 32);
    }
    g_mb[t] = make_uint2(lo, hi);
}

// ============================ KERNEL A: scores -> e + rowsums ============================
__global__ __launch_bounds__(NTH, 2)
void attn_a(const float* __restrict__ q)
{
    extern __shared__ uint32_t SW[];
    const uint32_t sb = smem_u32(SW);

    const int tid  = threadIdx.x;
    const int lane = tid & 31;
    const int w16  = (tid >> 5) * 16;
    const int g    = lane >> 2;
    const int tg   = lane & 3;

    const int h      = blockIdx.x;
    const int qblock = blockIdx.y;
    const int b      = blockIdx.z;
    const int bh     = b * HH + h;
    const int q0     = qblock * BM;
    const size_t head = (size_t)bh * SSEQ * DDIM;

    // stage K tile 0
    #pragma unroll
    for (int i = 0; i < 4; i++) {
        int chunk = i * NTH + tid;
        int row = chunk >> 4, c = chunk & 15;
        CP16(sb + KA_W(0) * 4 + row * 272 + c * 16,
             (const char*)g_kh + (head + (size_t)row * DDIM + c * 8) * 2);
    }
    CP_COMMIT();

    // stage Q tile, pre-scaled by scale*log2e, single fp16 plane
    {
        const float qsc = 0.08838834764831843f * 1.4426950408889634f;
        const float4* qp4 = (const float4*)(q + head + (size_t)q0 * DDIM);
        #pragma unroll
        for (int it = 0; it < 16; it++) {
            int idx = it * NTH + tid;
            int row = idx >> 5;
            int c4  = (idx & 31) << 2;
            float4 x = qp4[idx];
            int w = (row * QST + c4) >> 1;
            *(uint2*)(SW + QA_W + w) =
                make_uint2(pack_h2(x.x * qsc, x.y * qsc), pack_h2(x.z * qsc, x.w * qsc));
        }
    }

    const uint32_t a_byte  = (uint32_t)(((w16 + (lane & 15)) * QST + ((lane & 16) ? 8 : 0)) * 2);
    const uint32_t qhi_ad  = sb + QA_W * 4 + a_byte;
    const uint32_t bk_byte = (uint32_t)((((lane & 7) + ((lane & 16) ? 8 : 0)) * QST +
                                         ((lane & 8) ? 8 : 0)) * 2);

    const int r0 = q0 + w16 + g;
    const uint2* mbp = g_mb + ((size_t)b * SSEQ + r0) * NTILES;
    uint32_t* e0p = g_e + ((size_t)bh * SSEQ + r0) * (SSEQ / 2);
    uint32_t* e1p = e0p + (size_t)8 * (SSEQ / 2);

    float rsum0 = 0.f, rsum1 = 0.f;

    CP_WAIT0();
    __syncthreads();

    uint32_t qh[8][4];
    #pragma unroll
    for (int ks = 0; ks < 8; ks++)
        ldsm4(qh[ks][0], qh[ks][1], qh[ks][2], qh[ks][3], qhi_ad + ks * 32);

    for (int kb = 0; kb < NTILES; kb++) {
        const int buf = kb & 1;
        const int k0  = kb * BN;
        const bool pf = (kb + 1 < NTILES);

        if (pf) {
            #pragma unroll
            for (int i = 0; i < 4; i++) {
                int chunk = i * NTH + tid;
                int row = chunk >> 4, c = chunk & 15;
                CP16(sb + KA_W(buf ^ 1) * 4 + row * 272 + c * 16,
                     (const char*)g_kh +
                     (head + (size_t)(k0 + BN) * DDIM + (size_t)row * DDIM + c * 8) * 2);
            }
            CP_COMMIT();
        }

        const uint2 mb0 = mbp[kb];
        const uint2 mb1 = mbp[8 * NTILES + kb];
        const uint32_t k_ad = sb + KA_W(buf) * 4 + bk_byte;

        // score GEMM
        float sc[8][4];
        #pragma unroll
        for (int j = 0; j < 8; j++)
            #pragma unroll
            for (int p = 0; p < 4; p++) sc[j][p] = 0.f;
        #pragma unroll
        for (int ks = 0; ks < 8; ks++) {
            uint32_t bf[4][4];
            #pragma unroll
            for (int jp = 0; jp < 4; jp++)
                ldsm4(bf[jp][0], bf[jp][1], bf[jp][2], bf[jp][3],
                      k_ad + ks * 32 + jp * (16 * QST * 2));
            #pragma unroll
            for (int jp = 0; jp < 4; jp++) {
                mma_f16(sc[2 * jp],     qh[ks][0], qh[ks][1], qh[ks][2], qh[ks][3],
                        bf[jp][0], bf[jp][1]);
                mma_f16(sc[2 * jp + 1], qh[ks][0], qh[ks][1], qh[ks][2], qh[ks][3],
                        bf[jp][2], bf[jp][3]);
            }
        }

        // epilogue: masked exp -> rowsums + fp16 e to gmem
        #pragma unroll
        for (int j = 0; j < 8; j++) {
            uint32_t w0 = (j < 4) ? mb0.x : mb0.y;
            uint32_t w1 = (j < 4) ? mb1.x : mb1.y;
            int sh = tg * 2 + (j & 3) * 8;
            float e00 = ((w0 >> sh) & 1)       ? ex2f(sc[j][0]) : 0.f;
            float e01 = ((w0 >> (sh + 1)) & 1) ? ex2f(sc[j][1]) : 0.f;
            float e10 = ((w1 >> sh) & 1)       ? ex2f(sc[j][2]) : 0.f;
            float e11 = ((w1 >> (sh + 1)) & 1) ? ex2f(sc[j][3]) : 0.f;
            rsum0 += e00 + e01;
            rsum1 += e10 + e11;
            int wi = k0 / 2 + tg + j * 4;
            e0p[wi] = pack_h2(e00, e01);
            e1p[wi] = pack_h2(e10, e11);
        }

        if (pf) CP_WAIT0();
        __syncthreads();
    }

    rsum0 += __shfl_xor_sync(0xFFFFFFFF, rsum0, 1);
    rsum0 += __shfl_xor_sync(0xFFFFFFFF, rsum0, 2);
    rsum1 += __shfl_xor_sync(0xFFFFFFFF, rsum1, 1);
    rsum1 += __shfl_xor_sync(0xFFFFFFFF, rsum1, 2);
    if (tg == 0) {
        g_inv_rowsum[(size_t)bh * SSEQ + r0]     = 1.0f / rsum0;
        g_inv_rowsum[(size_t)bh * SSEQ + r0 + 8] = 1.0f / rsum1;
    }
}

// ============================ KERNEL B: PV + normalized attn ============================
__global__ __launch_bounds__(NTH, 2)
void attn_b(float* __restrict__ out, float* __restrict__ attn)
{
    extern __shared__ uint32_t SW[];
    const uint32_t sb = smem_u32(SW);

    const int tid  = threadIdx.x;
    const int lane = tid & 31;
    const int w16  = (tid >> 5) * 16;
    const int g    = lane >> 2;
    const int tg   = lane & 3;

    const int h      = blockIdx.x;
    const int qblock = blockIdx.y;
    const int b      = blockIdx.z;
    const int bh     = b * HH + h;
    const int q0     = qblock * BM;
    const size_t head = (size_t)bh * SSEQ * DDIM;
    const size_t row0_flat = (size_t)bh * SSEQ + q0;

    const uint32_t bv_byte = (uint32_t)((((lane & 7) + ((lane & 8) ? 8 : 0)) * QST) * 2 +
                                        ((lane & 16) ? 16 : 0));
    const uint32_t ea_byte = (uint32_t)(((w16 + (lane & 15)) * EST + ((lane & 16) ? 8 : 0)) * 2);

    const int r0 = q0 + w16 + g;
    float* a0p = attn + ((size_t)bh * SSEQ + r0) * SSEQ;
    float* a1p = a0p + (size_t)8 * SSEQ;
    const float inv0 = g_inv_rowsum[(size_t)bh * SSEQ + r0];
    const float inv1 = g_inv_rowsum[(size_t)bh * SSEQ + r0 + 8];

    float o[16][4];
    #pragma unroll
    for (int jn = 0; jn < 16; jn++)
        #pragma unroll
        for (int p = 0; p < 4; p++) o[jn][p] = 0.f;

    // stage e/V tile 0
    #pragma unroll
    for (int i = 0; i < 4; i++) {
        int chunk = i * NTH + tid;
        {   // e: 128 rows x 8 16B-chunks
            int row = chunk >> 3, cc = chunk & 7;
            CP16(sb + EB_W(0) * 4 + row * 144 + cc * 16,
                 (const char*)g_e + ((row0_flat + row) * SSEQ) * 2 + cc * 16);
        }
        {   // V: 64 rows x 16 16B-chunks
            int row = chunk >> 4, c = chunk & 15;
            CP16(sb + VB_W(0) * 4 + row * 272 + c * 16,
                 (const char*)g_vh + (head + (size_t)row * DDIM + c * 8) * 2);
        }
    }
    CP_COMMIT();
    CP_WAIT0();
    __syncthreads();

    for (int kb = 0; kb < NTILES; kb++) {
        const int buf = kb & 1;
        const int k0  = kb * BN;
        const bool pf = (kb + 1 < NTILES);

        if (pf) {
            #pragma unroll
            for (int i = 0; i < 4; i++) {
                int chunk = i * NTH + tid;
                {
                    int row = chunk >> 3, cc = chunk & 7;
                    CP16(sb + EB_W(buf ^ 1) * 4 + row * 144 + cc * 16,
                         (const char*)g_e + ((row0_flat + row) * SSEQ + (size_t)(k0 + BN)) * 2
                         + cc * 16);
                }
                {
                    int row = chunk >> 4, c = chunk & 15;
                    CP16(sb + VB_W(buf ^ 1) * 4 + row * 272 + c * 16,
                         (const char*)g_vh +
                         (head + (size_t)(k0 + BN) * DDIM + (size_t)row * DDIM + c * 8) * 2);
                }
            }
            CP_COMMIT();
        }

        // ---- e A-fragments (also carry the attn values for this tile) ----
        const uint32_t e_ad = sb + EB_W(buf) * 4 + ea_byte;
        const uint32_t v_ad = sb + VB_W(buf) * 4 + bv_byte;
        uint32_t ef[4][4];
        #pragma unroll
        for (int ks = 0; ks < 4; ks++)
            ldsm4(ef[ks][0], ef[ks][1], ef[ks][2], ef[ks][3], e_ad + ks * 32);

        // ---- PV MMAs ----
        #pragma unroll
        for (int ks = 0; ks < 4; ks++) {
            #pragma unroll
            for (int gjn = 0; gjn < 2; gjn++) {
                uint32_t vf[4][4];
                #pragma unroll
                for (int j = 0; j < 4; j++) {
                    int jnp = gjn * 4 + j;
                    ldsm4t(vf[j][0], vf[j][1], vf[j][2], vf[j][3],
                           v_ad + ks * (16 * QST * 2) + jnp * 32);
                }
                #pragma unroll
                for (int j = 0; j < 4; j++) {
                    int jnp = gjn * 4 + j;
                    mma_f16(o[2 * jnp],     ef[ks][0], ef[ks][1], ef[ks][2], ef[ks][3],
                            vf[j][0], vf[j][1]);
                    mma_f16(o[2 * jnp + 1], ef[ks][0], ef[ks][1], ef[ks][2], ef[ks][3],
                            vf[j][2], vf[j][3]);
                }
            }
        }

        // ---- attn write directly from the A-fragments (no smem re-read) ----
        // fragment layout: ef[ks][0]=(r0,   keys ks*16+tg*2), ef[ks][1]=(r0+8, same),
        //                  ef[ks][2]=(r0,   +8),              ef[ks][3]=(r0+8, +8)
        #pragma unroll
        for (int ks = 0; ks < 4; ks++) {
            const int c = k0 + ks * 16 + tg * 2;
            float2 f;
            f = __half22float2(*reinterpret_cast<const __half2*>(&ef[ks][0]));
            *(float2*)(a0p + c)     = make_float2(f.x * inv0, f.y * inv0);
            f = __half22float2(*reinterpret_cast<const __half2*>(&ef[ks][1]));
            *(float2*)(a1p + c)     = make_float2(f.x * inv1, f.y * inv1);
            f = __half22float2(*reinterpret_cast<const __half2*>(&ef[ks][2]));
            *(float2*)(a0p + c + 8) = make_float2(f.x * inv0, f.y * inv0);
            f = __half22float2(*reinterpret_cast<const __half2*>(&ef[ks][3]));
            *(float2*)(a1p + c + 8) = make_float2(f.x * inv1, f.y * inv1);
        }

        if (pf) CP_WAIT0();
        __syncthreads();
    }

    // normalized out
    float* o0p = out + ((size_t)bh * SSEQ + r0) * DDIM;
    float* o1p = o0p + (size_t)8 * DDIM;
    #pragma unroll
    for (int jn = 0; jn < 16; jn++) {
        const int c = jn * 8 + tg * 2;
        *(float2*)(o0p + c) = make_float2(o[jn][0] * inv0, o[jn][1] * inv0);
        *(float2*)(o1p + c) = make_float2(o[jn][2] * inv1, o[jn][3] * inv1);
    }
}

extern "C" void kernel_launch(void* const* d_in, const int* in_sizes, int n_in,
                              void* d_out, int out_size)
{
    const float* q    = (const float*)d_in[0];
    const float* k    = (const float*)d_in[1];
    const float* v    = (const float*)d_in[2];
    const int*   mask = (const int*)d_in[3];

    float* out  = (float*)d_out;
    float* attn = out + (size_t)BB * HH * SSEQ * DDIM;

    conv_kv<<<N4PLANE / 256, 256>>>((const float4*)k, (const float4*)v);
    conv_mask<<<NMB / 256, 256>>>(mask);

    cudaFuncSetAttribute(attn_a, cudaFuncAttributeMaxDynamicSharedMemorySize, SMEM_A_BYTES);
    cudaFuncSetAttribute(attn_b, cudaFuncAttributeMaxDynamicSharedMemorySize, SMEM_B_BYTES);

    dim3 grid(HH, SSEQ / BM, BB);
    attn_a<<<grid, NTH, SMEM_A_BYTES>>>(q);
    attn_b<<<grid, NTH, SMEM_B_BYTES>>>(out, attn);
}